// round 1
// baseline (speedup 1.0000x reference)
#include <cuda_runtime.h>

// GCN_8057358647356 — fp32 baseline with algebraic reduction.
// B=64 graphs, N=1024 nodes, F=128, H=256.
//
// Pipeline:
//   T  = adj @ X                      (batched, M=1024 N=128 K=1024)  -> S1
//   S  = relu(T @ W0 + b0)            (flat,    M=65536 N=256 K=128)  -> S2
//   U  = S @ W1                       (flat,    M=65536 N=256 K=256)  -> S1
//   V  = relu(adj @ U + b1)           (batched, M=1024 N=256 K=1024)  -> S2
//   z  = adj[:,0,:] @ V               (per-graph vector·matrix)       -> g_z
//   out= relu(z @ W2 + b2) @ Wl + bl  (tiny per-graph head)

#define BATCH 64
#define NNODE 1024
#define FEAT  128
#define HID   256

__device__ float g_S1[BATCH * NNODE * HID];   // 64 MB scratch (ping)
__device__ float g_S2[BATCH * NNODE * HID];   // 64 MB scratch (pong)
__device__ float g_z[BATCH * HID];

// ---------------------------------------------------------------------------
// 128x128 tile SGEMM, K-step 8, 256 threads, 8x8 accum per thread (4x4 quads).
// Optional fused bias + relu epilogue. Batched via blockIdx.z with strides.
// Requires: M,N multiples of 128; K multiple of 8; 16B-aligned rows (true here).
// ---------------------------------------------------------------------------
template <bool BIAS_RELU>
__global__ __launch_bounds__(256) void sgemm128(
    const float* __restrict__ A, const float* __restrict__ B,
    float* __restrict__ C, const float* __restrict__ bias,
    int M, int N, int K,
    long long sA, long long sB, long long sC)
{
    A += (long long)blockIdx.z * sA;
    B += (long long)blockIdx.z * sB;
    C += (long long)blockIdx.z * sC;

    __shared__ float As[8][128];
    __shared__ float Bs[8][128];

    const int tid = threadIdx.x;
    const int m0 = blockIdx.y * 128;
    const int n0 = blockIdx.x * 128;

    // A-tile load: 128 rows x 8 cols; each thread one float4 along K.
    const int arow = tid >> 1;
    const int acol = (tid & 1) * 4;
    // B-tile load: 8 rows x 128 cols; each thread one float4 along N.
    const int brow = tid >> 5;
    const int bcol = (tid & 31) * 4;

    const float* Ap = A + (long long)(m0 + arow) * K + acol;
    const float* Bp = B + (long long)brow * N + (n0 + bcol);

    const int tx = tid & 15;
    const int ty = tid >> 4;

    float acc[8][8];
#pragma unroll
    for (int i = 0; i < 8; i++)
#pragma unroll
        for (int j = 0; j < 8; j++) acc[i][j] = 0.f;

    for (int k = 0; k < K; k += 8) {
        float4 av = *(const float4*)(Ap + k);
        float4 bv = *(const float4*)(Bp + (long long)k * N);
        As[acol + 0][arow] = av.x;
        As[acol + 1][arow] = av.y;
        As[acol + 2][arow] = av.z;
        As[acol + 3][arow] = av.w;
        *(float4*)&Bs[brow][bcol] = bv;
        __syncthreads();

#pragma unroll
        for (int kk = 0; kk < 8; kk++) {
            float a[8], b[8];
            *(float4*)(a)     = *(const float4*)&As[kk][ty * 4];
            *(float4*)(a + 4) = *(const float4*)&As[kk][64 + ty * 4];
            *(float4*)(b)     = *(const float4*)&Bs[kk][tx * 4];
            *(float4*)(b + 4) = *(const float4*)&Bs[kk][64 + tx * 4];
#pragma unroll
            for (int i = 0; i < 8; i++)
#pragma unroll
                for (int j = 0; j < 8; j++)
                    acc[i][j] = fmaf(a[i], b[j], acc[i][j]);
        }
        __syncthreads();
    }

    // Epilogue: rows in two 64-row halves, cols in two 64-col halves.
#pragma unroll
    for (int i = 0; i < 8; i++) {
        const int r = m0 + ((i < 4) ? (ty * 4 + i) : (64 + ty * 4 + (i - 4)));
        float* Crow = C + (long long)r * N + n0;
#pragma unroll
        for (int half = 0; half < 2; half++) {
            const int cbase = half * 64 + tx * 4;
            float4 v;
            v.x = acc[i][half * 4 + 0];
            v.y = acc[i][half * 4 + 1];
            v.z = acc[i][half * 4 + 2];
            v.w = acc[i][half * 4 + 3];
            if (BIAS_RELU) {
                const float* bp = bias + n0 + cbase;
                v.x = fmaxf(v.x + bp[0], 0.f);
                v.y = fmaxf(v.y + bp[1], 0.f);
                v.z = fmaxf(v.z + bp[2], 0.f);
                v.w = fmaxf(v.w + bp[3], 0.f);
            }
            *(float4*)(Crow + cbase) = v;
        }
    }
}

// ---------------------------------------------------------------------------
// z[b,h] = sum_n adj[b,0,n] * V[b,n,h]   (adj row 0 dot against node dim)
// ---------------------------------------------------------------------------
__global__ __launch_bounds__(256) void rowdot_kernel(
    const float* __restrict__ adj, const float* __restrict__ V,
    float* __restrict__ z)
{
    const int b = blockIdx.x;
    const int h = threadIdx.x;   // 0..255
    __shared__ float ar[NNODE];
    for (int i = h; i < NNODE; i += 256)
        ar[i] = adj[(long long)b * NNODE * NNODE + i];
    __syncthreads();

    const float* vp = V + (long long)b * NNODE * HID + h;
    float a0 = 0.f, a1 = 0.f, a2 = 0.f, a3 = 0.f;
#pragma unroll 4
    for (int n = 0; n < NNODE; n += 4) {
        a0 = fmaf(ar[n + 0], vp[(long long)(n + 0) * HID], a0);
        a1 = fmaf(ar[n + 1], vp[(long long)(n + 1) * HID], a1);
        a2 = fmaf(ar[n + 2], vp[(long long)(n + 2) * HID], a2);
        a3 = fmaf(ar[n + 3], vp[(long long)(n + 3) * HID], a3);
    }
    z[b * HID + h] = (a0 + a1) + (a2 + a3);
}

// ---------------------------------------------------------------------------
// out[b,f] = (relu(z[b] @ W2 + b2)) @ Wl + bl
// ---------------------------------------------------------------------------
__global__ __launch_bounds__(256) void head_kernel(
    const float* __restrict__ z,
    const float* __restrict__ W2, const float* __restrict__ b2,
    const float* __restrict__ Wl, const float* __restrict__ bl,
    float* __restrict__ out)
{
    const int b = blockIdx.x;
    const int t = threadIdx.x;   // 0..255
    __shared__ float zs[HID], ts[HID];
    zs[t] = z[b * HID + t];
    __syncthreads();

    float acc = b2[t];
#pragma unroll 8
    for (int h = 0; h < HID; h++)
        acc = fmaf(zs[h], W2[h * HID + t], acc);
    ts[t] = fmaxf(acc, 0.f);
    __syncthreads();

    if (t < FEAT) {
        float o = bl[t];
#pragma unroll 8
        for (int h = 0; h < HID; h++)
            o = fmaf(ts[h], Wl[h * FEAT + t], o);
        out[b * FEAT + t] = o;
    }
}

// ---------------------------------------------------------------------------
extern "C" void kernel_launch(void* const* d_in, const int* in_sizes, int n_in,
                              void* d_out, int out_size)
{
    const float* embs = (const float*)d_in[0];  // [64,1024,128]
    const float* adj  = (const float*)d_in[1];  // [64,1024,1024]
    const float* W0   = (const float*)d_in[2];  // [128,256]
    const float* b0   = (const float*)d_in[3];  // [256]
    const float* W1   = (const float*)d_in[4];  // [256,256]
    const float* b1   = (const float*)d_in[5];  // [256]
    const float* W2   = (const float*)d_in[6];  // [256,256]
    const float* b2   = (const float*)d_in[7];  // [256]
    const float* Wl   = (const float*)d_in[8];  // [256,128]
    const float* bl   = (const float*)d_in[9];  // [128]
    float* out = (float*)d_out;                 // [64,128]

    float *S1, *S2, *z;
    cudaGetSymbolAddress((void**)&S1, g_S1);
    cudaGetSymbolAddress((void**)&S2, g_S2);
    cudaGetSymbolAddress((void**)&z,  g_z);

    dim3 blk(256);

    // 1) T = adj @ X : batched [1024 x 128], K=1024
    sgemm128<false><<<dim3(1, 8, 64), blk>>>(
        adj, embs, S1, nullptr,
        NNODE, FEAT, NNODE,
        (long long)NNODE * NNODE, (long long)NNODE * FEAT, (long long)NNODE * FEAT);

    // 2) S = relu(T @ W0 + b0) : flat [65536 x 256], K=128
    sgemm128<true><<<dim3(2, 512, 1), blk>>>(
        S1, W0, S2, b0,
        BATCH * NNODE, HID, FEAT, 0, 0, 0);

    // 3) U = S @ W1 : flat [65536 x 256], K=256
    sgemm128<false><<<dim3(2, 512, 1), blk>>>(
        S2, W1, S1, nullptr,
        BATCH * NNODE, HID, HID, 0, 0, 0);

    // 4) V = relu(adj @ U + b1) : batched [1024 x 256], K=1024
    sgemm128<true><<<dim3(2, 8, 64), blk>>>(
        adj, S1, S2, b1,
        NNODE, HID, NNODE,
        (long long)NNODE * NNODE, (long long)NNODE * HID, (long long)NNODE * HID);

    // 5) z = adj[:,0,:] @ V
    rowdot_kernel<<<64, 256>>>(adj, S2, z);

    // 6) out = relu(z @ W2 + b2) @ Wl + bl
    head_kernel<<<64, 256>>>(z, W2, b2, Wl, bl, out);
}